// round 1
// baseline (speedup 1.0000x reference)
#include <cuda_runtime.h>
#include <cuda_bf16.h>

// Problem constants (fixed shapes for this problem)
#define N_ROW  8192
#define N_COL  8192
#define RANK   256

// Scratch for row/col squared norms (no dynamic allocation allowed)
__device__ float g_x2[N_ROW];
__device__ float g_y2[N_COL];

// ---------------------------------------------------------------------------
// x2[i] = sum_k X[i][k]^2   (X is row-major [N_ROW, RANK], K contiguous)
// ---------------------------------------------------------------------------
__global__ void row_norms_kernel(const float* __restrict__ X) {
    int i = blockIdx.x * blockDim.x + threadIdx.x;
    if (i >= N_ROW) return;
    const float4* x = reinterpret_cast<const float4*>(X + (size_t)i * RANK);
    float s = 0.f;
#pragma unroll 16
    for (int k = 0; k < RANK / 4; ++k) {
        float4 v = x[k];
        s = fmaf(v.x, v.x, s);
        s = fmaf(v.y, v.y, s);
        s = fmaf(v.z, v.z, s);
        s = fmaf(v.w, v.w, s);
    }
    g_x2[i] = s;
}

// ---------------------------------------------------------------------------
// y2[j] = sum_k Y[k][j]^2   (Y is row-major [RANK, N_COL], N contiguous)
// ---------------------------------------------------------------------------
__global__ void col_norms_kernel(const float* __restrict__ Y) {
    int j = blockIdx.x * blockDim.x + threadIdx.x;
    if (j >= N_COL) return;
    float s = 0.f;
#pragma unroll 8
    for (int k = 0; k < RANK; ++k) {
        float v = Y[(size_t)k * N_COL + j];
        s = fmaf(v, v, s);
    }
    g_y2[j] = s;
}

// ---------------------------------------------------------------------------
// Fused SGEMM + epilogue:
//   cross = X @ Y
//   z     = beta - sqrt(max(x2[i] + y2[j] - 2*cross, 0))
//
// 128x128 block tile, BK=8, 256 threads, 8x8 outputs per thread arranged as
// 2x2 quads of float4 (rows {tr*4, tr*4+64}, cols {tc*4, tc*4+64}) so shared
// loads are conflict-free float4 and stores are float4.
// Double-buffered smem, one __syncthreads per K-tile.
// ---------------------------------------------------------------------------
__global__ __launch_bounds__(256, 2)
void l2_gemm_kernel(const float* __restrict__ X,
                    const float* __restrict__ Y,
                    const float* __restrict__ beta,
                    float* __restrict__ out) {
    __shared__ float As[2][8][128];   // [buf][k][m]  (transposed A tile)
    __shared__ float Bs[2][8][128];   // [buf][k][n]

    const int tid  = threadIdx.x;
    const int tr   = tid >> 4;        // 0..15  (row group)
    const int tc   = tid & 15;        // 0..15  (col group)
    const int brow = blockIdx.y * 128;
    const int bcol = blockIdx.x * 128;

    // Global-load assignments (one float4 per thread per tile, for A and B)
    const int a_row  = tid >> 1;          // 0..127
    const int a_col4 = (tid & 1) * 4;     // 0 or 4
    const int b_krow = tid >> 5;          // 0..7
    const int b_col4 = (tid & 31) * 4;    // 0..124

    const float* Aptr = X + (size_t)(brow + a_row) * RANK + a_col4;
    const float* Bptr = Y + (size_t)b_krow * N_COL + bcol + b_col4;

    float acc[8][8];
#pragma unroll
    for (int i = 0; i < 8; ++i)
#pragma unroll
        for (int j = 0; j < 8; ++j) acc[i][j] = 0.f;

    // --- preload tile 0 into buffer 0 ---
    {
        float4 av = *reinterpret_cast<const float4*>(Aptr);
        float4 bv = *reinterpret_cast<const float4*>(Bptr);
        As[0][a_col4 + 0][a_row] = av.x;
        As[0][a_col4 + 1][a_row] = av.y;
        As[0][a_col4 + 2][a_row] = av.z;
        As[0][a_col4 + 3][a_row] = av.w;
        *reinterpret_cast<float4*>(&Bs[0][b_krow][b_col4]) = bv;
    }
    __syncthreads();

    const int NKT = RANK / 8;  // 32 K-tiles
#pragma unroll 1
    for (int kt = 0; kt < NKT; ++kt) {
        const int cur = kt & 1;
        const int nxt = cur ^ 1;

        float4 av, bv;
        if (kt < NKT - 1) {
            av = *reinterpret_cast<const float4*>(Aptr + (kt + 1) * 8);
            bv = *reinterpret_cast<const float4*>(Bptr + (size_t)(kt + 1) * 8 * N_COL);
        }

#pragma unroll
        for (int k = 0; k < 8; ++k) {
            float a[8], b[8];
            *reinterpret_cast<float4*>(&a[0]) =
                *reinterpret_cast<const float4*>(&As[cur][k][tr * 4]);
            *reinterpret_cast<float4*>(&a[4]) =
                *reinterpret_cast<const float4*>(&As[cur][k][tr * 4 + 64]);
            *reinterpret_cast<float4*>(&b[0]) =
                *reinterpret_cast<const float4*>(&Bs[cur][k][tc * 4]);
            *reinterpret_cast<float4*>(&b[4]) =
                *reinterpret_cast<const float4*>(&Bs[cur][k][tc * 4 + 64]);
#pragma unroll
            for (int i = 0; i < 8; ++i)
#pragma unroll
                for (int j = 0; j < 8; ++j)
                    acc[i][j] = fmaf(a[i], b[j], acc[i][j]);
        }

        if (kt < NKT - 1) {
            As[nxt][a_col4 + 0][a_row] = av.x;
            As[nxt][a_col4 + 1][a_row] = av.y;
            As[nxt][a_col4 + 2][a_row] = av.z;
            As[nxt][a_col4 + 3][a_row] = av.w;
            *reinterpret_cast<float4*>(&Bs[nxt][b_krow][b_col4]) = bv;
            __syncthreads();
        }
    }

    // --- fused epilogue: z = beta - sqrt(max(x2 + y2 - 2*cross, 0)) ---
    const float beta_v = __ldg(beta);

    float xr[8], yc[8];
#pragma unroll
    for (int i = 0; i < 8; ++i) {
        int r = (i < 4) ? (tr * 4 + i) : (tr * 4 + 64 + (i - 4));
        xr[i] = g_x2[brow + r];
    }
#pragma unroll
    for (int j = 0; j < 8; ++j) {
        int c = (j < 4) ? (tc * 4 + j) : (tc * 4 + 64 + (j - 4));
        yc[j] = g_y2[bcol + c];
    }

#pragma unroll
    for (int i = 0; i < 8; ++i) {
        int r = (i < 4) ? (tr * 4 + i) : (tr * 4 + 64 + (i - 4));
        float* orow = out + (size_t)(brow + r) * N_COL + bcol;
        float z[8];
#pragma unroll
        for (int j = 0; j < 8; ++j) {
            float d2 = xr[i] + yc[j] - 2.f * acc[i][j];
            d2 = fmaxf(d2, 0.f);
            z[j] = beta_v - sqrtf(d2);
        }
        *reinterpret_cast<float4*>(orow + tc * 4)      = *reinterpret_cast<float4*>(&z[0]);
        *reinterpret_cast<float4*>(orow + tc * 4 + 64) = *reinterpret_cast<float4*>(&z[4]);
    }
}

// ---------------------------------------------------------------------------
extern "C" void kernel_launch(void* const* d_in, const int* in_sizes, int n_in,
                              void* d_out, int out_size) {
    const float* X    = (const float*)d_in[0];  // [8192, 256]
    const float* Y    = (const float*)d_in[1];  // [256, 8192]
    const float* beta = (const float*)d_in[2];  // [1]
    float* out        = (float*)d_out;          // [8192, 8192]

    row_norms_kernel<<<N_ROW / 256, 256>>>(X);
    col_norms_kernel<<<N_COL / 256, 256>>>(Y);

    dim3 grid(N_COL / 128, N_ROW / 128);
    l2_gemm_kernel<<<grid, 256>>>(X, Y, beta, out);
}